// round 5
// baseline (speedup 1.0000x reference)
#include <cuda_runtime.h>
#include <cuda_bf16.h>
#include <math.h>

#define B_ 4
#define T_ 2048
#define D_ 256
#define H_ 4
#define HD_ 64
#define L_ 2
#define NQ_ 128          // 2*MAX_BITS out queries
#define MLPH_ 64

// ---------------- device scratch (no allocations allowed) ----------------
__device__ float g_x   [B_*T_*D_];        // residual stream
__device__ float g_h   [B_*T_*D_];        // ln out / attn out / lnf out
__device__ float g_qkv [B_*T_*3*D_];      // qkv projections
__device__ float g_ffn [(size_t)B_*T_*4*D_]; // ffn hidden
__device__ float g_sel [B_*NQ_*D_];       // selected vectors
__device__ float g_qs  [(size_t)B_*T_*NQ_]; // raw query scores [t][q]
__device__ float g_bits[B_*NQ_];

// ---------------- embed ----------------
__global__ void embed_kernel(const int* __restrict__ tokens,
                             const float* __restrict__ emb,
                             float* __restrict__ x) {
    int i = blockIdx.x * 256 + threadIdx.x;
    if (i >= B_*T_*D_) return;
    int d = i & (D_-1);
    int bt = i >> 8;
    x[i] = emb[tokens[bt]*D_ + d];
}

// ---------------- layernorm (one row per block, 256 threads) ----------------
__global__ void layernorm_kernel(const float* __restrict__ x,
                                 const float* __restrict__ w,
                                 const float* __restrict__ b,
                                 float* __restrict__ y) {
    int row = blockIdx.x;
    int tid = threadIdx.x;
    const float* xr = x + (size_t)row * D_;
    float v = xr[tid];
    __shared__ float red[8];
    float s = v;
    #pragma unroll
    for (int o = 16; o > 0; o >>= 1) s += __shfl_xor_sync(0xffffffffu, s, o);
    if ((tid & 31) == 0) red[tid >> 5] = s;
    __syncthreads();
    float tot = 0.f;
    #pragma unroll
    for (int i = 0; i < 8; i++) tot += red[i];
    float mean = tot * (1.f/256.f);
    float d = v - mean;
    float sq = d * d;
    __syncthreads();
    float s2 = sq;
    #pragma unroll
    for (int o = 16; o > 0; o >>= 1) s2 += __shfl_xor_sync(0xffffffffu, s2, o);
    if ((tid & 31) == 0) red[tid >> 5] = s2;
    __syncthreads();
    float tot2 = 0.f;
    #pragma unroll
    for (int i = 0; i < 8; i++) tot2 += red[i];
    float var = tot2 * (1.f/256.f);
    y[(size_t)row * D_ + tid] = d * rsqrtf(var + 1e-5f) * w[tid] + b[tid];
}

// ---------------- tiled SGEMM: C = act(alpha*A@W + bias) (+resid) ----------------
// BM=BN=128, BK=16, 256 threads, 8x8 microtile.
// ACT: 0 none, 1 exact GELU.  RES: add resid.  WT: W stored [N][K] (transposed).
template<int ACT, bool RES, bool WT>
__global__ __launch_bounds__(256)
void sgemm_kernel(const float* __restrict__ A, const float* __restrict__ W,
                  const float* __restrict__ bias, const float* __restrict__ resid,
                  float* __restrict__ C, int M, int N, int K, float alpha) {
    __shared__ float Ast[16][128];  // [kk][row]
    __shared__ float Ws [16][128];  // [kk][col]
    int tid = threadIdx.x;
    int tx = tid & 15, ty = tid >> 4;
    int bm = blockIdx.y * 128, bn = blockIdx.x * 128;
    float acc[8][8] = {};
    for (int k0 = 0; k0 < K; k0 += 16) {
        #pragma unroll
        for (int i = 0; i < 2; i++) {
            int fi = tid + i * 256;           // 512 float4s = 128x16
            int r = fi >> 2, cg = (fi & 3) << 2;
            float4 va = *(const float4*)(A + (size_t)(bm + r) * K + k0 + cg);
            Ast[cg+0][r] = va.x; Ast[cg+1][r] = va.y;
            Ast[cg+2][r] = va.z; Ast[cg+3][r] = va.w;
        }
        if (!WT) {
            #pragma unroll
            for (int i = 0; i < 2; i++) {
                int fi = tid + i * 256;       // 512 float4s = 16x128
                int r = fi >> 5, cg = (fi & 31) << 2;
                *(float4*)(&Ws[r][cg]) = *(const float4*)(W + (size_t)(k0 + r) * N + bn + cg);
            }
        } else {
            #pragma unroll
            for (int i = 0; i < 8; i++) {
                int idx = tid + i * 256;
                int r = idx >> 7, c = idx & 127;
                Ws[r][c] = W[(size_t)(bn + c) * K + k0 + r];
            }
        }
        __syncthreads();
        #pragma unroll
        for (int kk = 0; kk < 16; kk++) {
            float a[8], w[8];
            *(float4*)&a[0] = *(float4*)&Ast[kk][ty*8];
            *(float4*)&a[4] = *(float4*)&Ast[kk][ty*8+4];
            *(float4*)&w[0] = *(float4*)&Ws[kk][tx*8];
            *(float4*)&w[4] = *(float4*)&Ws[kk][tx*8+4];
            #pragma unroll
            for (int i = 0; i < 8; i++)
                #pragma unroll
                for (int j = 0; j < 8; j++)
                    acc[i][j] += a[i] * w[j];
        }
        __syncthreads();
    }
    #pragma unroll
    for (int i = 0; i < 8; i++) {
        int r = bm + ty*8 + i;
        #pragma unroll
        for (int j = 0; j < 8; j++) {
            int c = bn + tx*8 + j;
            float v = acc[i][j] * alpha + (bias ? bias[c] : 0.f);
            if (ACT == 1) v = 0.5f * v * (1.f + erff(v * 0.70710678118654752f));
            if (RES) v += resid[(size_t)r * N + c];
            C[(size_t)r * N + c] = v;
        }
    }
}

// ---------------- RoPE applied in-place to q,k inside qkv ----------------
__global__ void rope_kernel(float* __restrict__ qkv) {
    int idx = blockIdx.x * 256 + threadIdx.x;   // B*T*H*32
    if (idx >= B_*T_*H_*32) return;
    int d = idx & 31;
    int h = (idx >> 5) & (H_-1);
    int bt = idx >> 7;                 // b*T + t
    int t = bt & (T_-1);
    float invf = powf(10000.f, -(float)d * (1.f/32.f));
    float ang = (float)t * invf;
    float sv, cv;
    sincosf(ang, &sv, &cv);
    float* base = qkv + (size_t)bt * (3*D_);
    float* q = base + h * HD_;
    float q1 = q[d], q2 = q[d+32];
    q[d]    = q1*cv - q2*sv;
    q[d+32] = q2*cv + q1*sv;
    float* k = base + D_ + h * HD_;
    float k1 = k[d], k2 = k[d+32];
    k[d]    = k1*cv - k2*sv;
    k[d+32] = k2*cv + k1*sv;
}

// ---------------- fused causal flash attention ----------------
// grid (T/64, H, B), 256 threads, dynamic smem.
#define ATTN_SMEM ((4*64*65 + 3*64) * 4)
__global__ __launch_bounds__(256)
void attn_kernel(const float* __restrict__ qkv, float* __restrict__ out) {
    extern __shared__ float sm[];
    float* Qs  = sm;                // [r][d] 64x65
    float* Ks  = Qs + 64*65;        // [d][c] 64x65
    float* Vs  = Ks + 64*65;        // [s][d] 64x65
    float* S   = Vs + 64*65;        // [r][c] 64x65
    float* mrow = S + 64*65;
    float* lrow = mrow + 64;
    float* rfac = lrow + 64;
    int qt = blockIdx.x, h = blockIdx.y, b = blockIdx.z;
    int tid = threadIdx.x;
    int tx = tid & 15, ty = tid >> 4;

    for (int i = tid; i < 64*64; i += 256) {
        int r = i >> 6, d = i & 63;
        int t = qt*64 + r;
        Qs[r*65 + d] = qkv[(size_t)(b*T_ + t) * (3*D_) + h*HD_ + d];
    }
    if (tid < 64) { mrow[tid] = -INFINITY; lrow[tid] = 0.f; }
    float O[4][4] = {};
    __syncthreads();

    for (int kt = 0; kt <= qt; kt++) {
        for (int i = tid; i < 64*64; i += 256) {
            int s = i >> 6, d = i & 63;
            int t = kt*64 + s;
            const float* base = qkv + (size_t)(b*T_ + t) * (3*D_);
            Ks[d*65 + s] = base[D_   + h*HD_ + d];
            Vs[s*65 + d] = base[2*D_ + h*HD_ + d];
        }
        __syncthreads();
        float acc[4][4] = {};
        #pragma unroll
        for (int d = 0; d < 64; d++) {
            float a[4], kv[4];
            #pragma unroll
            for (int i = 0; i < 4; i++) a[i]  = Qs[(ty*4+i)*65 + d];
            #pragma unroll
            for (int j = 0; j < 4; j++) kv[j] = Ks[d*65 + tx*4+j];
            #pragma unroll
            for (int i = 0; i < 4; i++)
                #pragma unroll
                for (int j = 0; j < 4; j++) acc[i][j] += a[i]*kv[j];
        }
        #pragma unroll
        for (int i = 0; i < 4; i++)
            #pragma unroll
            for (int j = 0; j < 4; j++) {
                int r = ty*4+i, c = tx*4+j;
                float v = acc[i][j] * 0.125f;
                if (kt == qt && c > r) v = -INFINITY;
                S[r*65 + c] = v;
            }
        __syncthreads();
        if (tid < 64) {
            int r = tid;
            float mo = mrow[r];
            float mx = mo;
            #pragma unroll 8
            for (int c = 0; c < 64; c++) mx = fmaxf(mx, S[r*65 + c]);
            float rf = expf(mo - mx);            // exp(-inf)=0 on first tile
            float ls = 0.f;
            #pragma unroll 8
            for (int c = 0; c < 64; c++) {
                float e = expf(S[r*65 + c] - mx);
                S[r*65 + c] = e;
                ls += e;
            }
            lrow[r] = lrow[r]*rf + ls;
            mrow[r] = mx;
            rfac[r] = rf;
        }
        __syncthreads();
        float rf_[4];
        #pragma unroll
        for (int i = 0; i < 4; i++) rf_[i] = rfac[ty*4+i];
        #pragma unroll
        for (int i = 0; i < 4; i++)
            #pragma unroll
            for (int j = 0; j < 4; j++) O[i][j] *= rf_[i];
        #pragma unroll
        for (int s = 0; s < 64; s++) {
            float p[4], vv[4];
            #pragma unroll
            for (int i = 0; i < 4; i++) p[i]  = S[(ty*4+i)*65 + s];
            #pragma unroll
            for (int j = 0; j < 4; j++) vv[j] = Vs[s*65 + tx*4+j];
            #pragma unroll
            for (int i = 0; i < 4; i++)
                #pragma unroll
                for (int j = 0; j < 4; j++) O[i][j] += p[i]*vv[j];
        }
        __syncthreads();
    }
    #pragma unroll
    for (int i = 0; i < 4; i++) {
        int r = ty*4 + i;
        float inv = 1.f / lrow[r];
        int t = qt*64 + r;
        #pragma unroll
        for (int j = 0; j < 4; j++)
            out[(size_t)(b*T_ + t) * D_ + h*HD_ + tx*4 + j] = O[i][j] * inv;
    }
}

// ---------------- query-attention softmax: scores[t][q] -> p[b,q,t] ----------------
__global__ void qsoftmax_kernel(const float* __restrict__ scores, float* __restrict__ p) {
    int bq = blockIdx.x;           // b*128 + q
    int b = bq >> 7, q = bq & 127;
    int tid = threadIdx.x;         // 256
    __shared__ float red[8];
    float vals[8];
    float lmax = -INFINITY;
    #pragma unroll
    for (int i = 0; i < 8; i++) {
        int t = tid + i*256;
        float s = scores[(size_t)(b*T_ + t) * NQ_ + q];
        vals[i] = s;
        lmax = fmaxf(lmax, s);
    }
    #pragma unroll
    for (int o = 16; o > 0; o >>= 1) lmax = fmaxf(lmax, __shfl_xor_sync(0xffffffffu, lmax, o));
    if ((tid & 31) == 0) red[tid >> 5] = lmax;
    __syncthreads();
    float bmax = -INFINITY;
    #pragma unroll
    for (int i = 0; i < 8; i++) bmax = fmaxf(bmax, red[i]);
    float lsum = 0.f;
    #pragma unroll
    for (int i = 0; i < 8; i++) { vals[i] = expf(vals[i] - bmax); lsum += vals[i]; }
    __syncthreads();
    #pragma unroll
    for (int o = 16; o > 0; o >>= 1) lsum += __shfl_xor_sync(0xffffffffu, lsum, o);
    if ((tid & 31) == 0) red[tid >> 5] = lsum;
    __syncthreads();
    float bsum = 0.f;
    #pragma unroll
    for (int i = 0; i < 8; i++) bsum += red[i];
    float inv = 1.f / bsum;
    #pragma unroll
    for (int i = 0; i < 8; i++)
        p[(size_t)bq * T_ + tid + i*256] = vals[i] * inv;
}

// ---------------- selected[b,q,:] = sum_t p[b,q,t] * xf[b,t,:] ----------------
// block handles 8 queries of one batch; thread owns one dim d.
__global__ void selected_kernel(const float* __restrict__ xf, const float* __restrict__ p,
                                float* __restrict__ sel) {
    int blk = blockIdx.x;                 // B*16
    int b = blk >> 4, qg = (blk & 15) * 8;
    int d = threadIdx.x;
    __shared__ float ps[8][257];
    float acc[8] = {};
    for (int t0 = 0; t0 < T_; t0 += 256) {
        #pragma unroll
        for (int g = 0; g < 8; g++)
            ps[g][threadIdx.x] = p[(size_t)(b*NQ_ + qg + g) * T_ + t0 + threadIdx.x];
        __syncthreads();
        for (int tt = 0; tt < 256; tt++) {
            float xv = xf[(size_t)(b*T_ + t0 + tt) * D_ + d];
            #pragma unroll
            for (int g = 0; g < 8; g++) acc[g] += ps[g][tt] * xv;
        }
        __syncthreads();
    }
    #pragma unroll
    for (int g = 0; g < 8; g++)
        sel[(size_t)(b*NQ_ + qg + g) * D_ + d] = acc[g];
}

// ---------------- bits = sigmoid(selected @ outp_w + b) ----------------
__global__ void bits_kernel(const float* __restrict__ sel, const float* __restrict__ w,
                            const float* __restrict__ b0,
                            float* __restrict__ pairs_out, float* __restrict__ bits_sc) {
    int i = threadIdx.x;                  // 512 = B*NQ
    float s = b0[0];
    const float* sr = sel + (size_t)i * D_;
    for (int d = 0; d < D_; d++) s += sr[d] * w[d];
    float bit = 1.f / (1.f + expf(-s));
    pairs_out[i] = bit;
    bits_sc[i] = bit;
}

// ---------------- 64-step sequential MLP scan ----------------
__global__ void scan_kernel(const float* __restrict__ pairs,
                            const float* __restrict__ w1, const float* __restrict__ b1,
                            const float* __restrict__ w2, const float* __restrict__ b2,
                            const float* __restrict__ w3, const float* __restrict__ b3,
                            float* __restrict__ sum_all) {
    int tid = threadIdx.x;                // 256 = 4 batch * 64 units
    int bb = tid >> 6, u = tid & 63;
    __shared__ float h1[4][65];
    __shared__ float h2s[4][65];
    __shared__ float carry[4];
    if (u == 0) carry[bb] = 0.f;
    __syncthreads();
    for (int step = 0; step < 64; step++) {
        float a  = pairs[bb*128 + step*2 + 0];
        float bv = pairs[bb*128 + step*2 + 1];
        float cz = carry[bb];
        float h = a*w1[0*64+u] + bv*w1[1*64+u] + cz*w1[2*64+u] + b1[u];
        h1[bb][u] = fmaxf(h, 0.f);
        __syncthreads();
        float h2 = b2[u];
        #pragma unroll 8
        for (int j = 0; j < 64; j++) h2 += h1[bb][j] * w2[j*64+u];
        h2s[bb][u] = fmaxf(h2, 0.f);
        __syncthreads();
        if (u < 2) {
            float o = b3[u];
            #pragma unroll 8
            for (int j = 0; j < 64; j++) o += h2s[bb][j] * w3[j*2+u];
            o = 1.f / (1.f + expf(-o));
            if (u == 0) sum_all[bb*65 + step] = o;
            else        carry[bb] = o;
        }
        __syncthreads();
    }
    if (u == 0) sum_all[bb*65 + 64] = carry[bb];
}

// ---------------- host launcher ----------------
extern "C" void kernel_launch(void* const* d_in, const int* in_sizes, int n_in,
                              void* d_out, int out_size) {
    const int*   tokens = (const int*)  d_in[0];
    const float* embedw = (const float*)d_in[1];
    const float* ln1_w  = (const float*)d_in[2];
    const float* ln1_b  = (const float*)d_in[3];
    const float* qkv_w  = (const float*)d_in[4];
    const float* qkv_b  = (const float*)d_in[5];
    const float* proj_w = (const float*)d_in[6];
    const float* proj_b = (const float*)d_in[7];
    const float* ln2_w  = (const float*)d_in[8];
    const float* ln2_b  = (const float*)d_in[9];
    const float* ffn1_w = (const float*)d_in[10];
    const float* ffn1_b = (const float*)d_in[11];
    const float* ffn2_w = (const float*)d_in[12];
    const float* ffn2_b = (const float*)d_in[13];
    const float* lnf_w  = (const float*)d_in[14];
    const float* lnf_b  = (const float*)d_in[15];
    const float* oq     = (const float*)d_in[16];
    const float* outp_w = (const float*)d_in[17];
    const float* outp_b = (const float*)d_in[18];
    const float* mlp_w1 = (const float*)d_in[19];
    const float* mlp_b1 = (const float*)d_in[20];
    const float* mlp_w2 = (const float*)d_in[21];
    const float* mlp_b2 = (const float*)d_in[22];
    const float* mlp_w3 = (const float*)d_in[23];
    const float* mlp_b3 = (const float*)d_in[24];

    float* out       = (float*)d_out;
    float* out_sum   = out;                 // 4*65   = 260
    float* out_pairs = out + 260;           // 4*64*2 = 512
    float* out_p     = out + 772;           // 4*128*2048

    float *x, *h, *qkv, *ffn, *sel, *qs, *bits;
    cudaGetSymbolAddress((void**)&x,    g_x);
    cudaGetSymbolAddress((void**)&h,    g_h);
    cudaGetSymbolAddress((void**)&qkv,  g_qkv);
    cudaGetSymbolAddress((void**)&ffn,  g_ffn);
    cudaGetSymbolAddress((void**)&sel,  g_sel);
    cudaGetSymbolAddress((void**)&qs,   g_qs);
    cudaGetSymbolAddress((void**)&bits, g_bits);

    cudaFuncSetAttribute(attn_kernel, cudaFuncAttributeMaxDynamicSharedMemorySize, ATTN_SMEM);

    const int M = B_*T_;   // 8192

    embed_kernel<<<(B_*T_*D_ + 255)/256, 256>>>(tokens, embedw, x);

    for (int l = 0; l < L_; l++) {
        layernorm_kernel<<<M, 256>>>(x, ln1_w + l*D_, ln1_b + l*D_, h);
        sgemm_kernel<0,false,false><<<dim3(6, 64), 256>>>(
            h, qkv_w + (size_t)l*D_*3*D_, qkv_b + l*3*D_, nullptr, qkv, M, 3*D_, D_, 1.f);
        rope_kernel<<<(B_*T_*H_*32 + 255)/256, 256>>>(qkv);
        attn_kernel<<<dim3(T_/64, H_, B_), 256, ATTN_SMEM>>>(qkv, h);
        sgemm_kernel<0,true,false><<<dim3(2, 64), 256>>>(
            h, proj_w + (size_t)l*D_*D_, proj_b + l*D_, x, x, M, D_, D_, 1.f);
        layernorm_kernel<<<M, 256>>>(x, ln2_w + l*D_, ln2_b + l*D_, h);
        sgemm_kernel<1,false,false><<<dim3(8, 64), 256>>>(
            h, ffn1_w + (size_t)l*D_*4*D_, ffn1_b + l*4*D_, nullptr, ffn, M, 4*D_, D_, 1.f);
        sgemm_kernel<0,true,false><<<dim3(2, 64), 256>>>(
            ffn, ffn2_w + (size_t)l*4*D_*D_, ffn2_b + l*D_, x, x, M, D_, 4*D_, 1.f);
    }

    layernorm_kernel<<<M, 256>>>(x, lnf_w, lnf_b, h);

    // q_scores = xf @ oq^T / 16  -> [t][q]
    sgemm_kernel<0,false,true><<<dim3(1, 64), 256>>>(
        h, oq, nullptr, nullptr, qs, M, NQ_, D_, 0.0625f);
    qsoftmax_kernel<<<B_*NQ_, 256>>>(qs, out_p);
    selected_kernel<<<B_*16, 256>>>(h, out_p, sel);
    bits_kernel<<<1, 512>>>(sel, outp_w, outp_b, out_pairs, bits);
    scan_kernel<<<1, 256>>>(bits, mlp_w1, mlp_b1, mlp_w2, mlp_b2, mlp_w3, mlp_b3, out_sum);
}

// round 6
// speedup vs baseline: 1.8682x; 1.8682x over previous
#include <cuda_runtime.h>
#include <cuda_bf16.h>
#include <math.h>

#define B_ 4
#define T_ 2048
#define D_ 256
#define H_ 4
#define HD_ 64
#define L_ 2
#define NQ_ 128
#define MLPH_ 64

// ---------------- device scratch ----------------
__device__ float g_x   [B_*T_*D_];
__device__ float g_h   [B_*T_*D_];
__device__ float g_qkv [B_*T_*3*D_];
__device__ float g_ffn [(size_t)B_*T_*4*D_];
__device__ float g_sel [B_*NQ_*D_];
__device__ float g_qs  [(size_t)B_*T_*NQ_];
__device__ float g_bits[B_*NQ_];

// ---------------- tf32 helpers ----------------
__device__ __forceinline__ unsigned f2tf(float f) {
    unsigned u; asm("cvt.rna.tf32.f32 %0, %1;" : "=r"(u) : "f"(f)); return u;
}
__device__ __forceinline__ void mma_tf32(float* c, const unsigned* a, const unsigned* b) {
    asm volatile("mma.sync.aligned.m16n8k8.row.col.f32.tf32.tf32.f32 "
        "{%0,%1,%2,%3}, {%4,%5,%6,%7}, {%8,%9}, {%0,%1,%2,%3};"
        : "+f"(c[0]), "+f"(c[1]), "+f"(c[2]), "+f"(c[3])
        : "r"(a[0]), "r"(a[1]), "r"(a[2]), "r"(a[3]), "r"(b[0]), "r"(b[1]));
}

// ---------------- embed ----------------
__global__ void embed_kernel(const int* __restrict__ tokens,
                             const float* __restrict__ emb,
                             float* __restrict__ x) {
    int i = blockIdx.x * 256 + threadIdx.x;
    if (i >= B_*T_*D_) return;
    int d = i & (D_-1);
    int bt = i >> 8;
    x[i] = emb[tokens[bt]*D_ + d];
}

// ---------------- layernorm ----------------
__global__ void layernorm_kernel(const float* __restrict__ x,
                                 const float* __restrict__ w,
                                 const float* __restrict__ b,
                                 float* __restrict__ y) {
    int row = blockIdx.x;
    int tid = threadIdx.x;
    const float* xr = x + (size_t)row * D_;
    float v = xr[tid];
    __shared__ float red[8];
    float s = v;
    #pragma unroll
    for (int o = 16; o > 0; o >>= 1) s += __shfl_xor_sync(0xffffffffu, s, o);
    if ((tid & 31) == 0) red[tid >> 5] = s;
    __syncthreads();
    float tot = 0.f;
    #pragma unroll
    for (int i = 0; i < 8; i++) tot += red[i];
    float mean = tot * (1.f/256.f);
    float d = v - mean;
    float sq = d * d;
    __syncthreads();
    float s2 = sq;
    #pragma unroll
    for (int o = 16; o > 0; o >>= 1) s2 += __shfl_xor_sync(0xffffffffu, s2, o);
    if ((tid & 31) == 0) red[tid >> 5] = s2;
    __syncthreads();
    float tot2 = 0.f;
    #pragma unroll
    for (int i = 0; i < 8; i++) tot2 += red[i];
    float var = tot2 * (1.f/256.f);
    y[(size_t)row * D_ + tid] = d * rsqrtf(var + 1e-5f) * w[tid] + b[tid];
}

// ---------------- tf32 tensor-core GEMM ----------------
// C = act(alpha*A@W + bias) (+resid).  BM=BN=128, BK=16, 256 thr, 8 warps (2x4),
// warp tile 64x32, mma m16n8k8 tf32, double-buffered smem.
template<int ACT, bool RES>
__global__ __launch_bounds__(256)
void gemm_tf32_kernel(const float* __restrict__ A, const float* __restrict__ W,
                      const float* __restrict__ bias, const float* __restrict__ resid,
                      float* __restrict__ C, int M, int N, int K, float alpha) {
    __shared__ unsigned Ast[2][16][132];   // [k][m], stride 132 (==4 mod 32: conflict-free frags)
    __shared__ unsigned Ws [2][16][132];   // [k][n]
    int tid = threadIdx.x;
    int w = tid >> 5, lane = tid & 31;
    int g = lane >> 2, q = lane & 3;
    int wm = (w >> 2) * 64, wn = (w & 3) * 32;
    int bm = blockIdx.y * 128, bn = blockIdx.x * 128;

    float acc[4][4][4] = {};               // [mf][nf][c0..c3]
    float4 aR[2], bR[2];

    // tile 0 -> buf 0
    #pragma unroll
    for (int i = 0; i < 2; i++) {
        int fi = tid + i*256;
        int r = fi >> 2, kg = (fi & 3) << 2;
        aR[i] = *(const float4*)(A + (size_t)(bm + r) * K + kg);
        int r2 = fi >> 5, cg = (fi & 31) << 2;
        bR[i] = *(const float4*)(W + (size_t)r2 * N + bn + cg);
    }
    #pragma unroll
    for (int i = 0; i < 2; i++) {
        int fi = tid + i*256;
        int r = fi >> 2, kg = (fi & 3) << 2;
        Ast[0][kg+0][r] = f2tf(aR[i].x); Ast[0][kg+1][r] = f2tf(aR[i].y);
        Ast[0][kg+2][r] = f2tf(aR[i].z); Ast[0][kg+3][r] = f2tf(aR[i].w);
        int r2 = fi >> 5, cg = (fi & 31) << 2;
        Ws[0][r2][cg+0] = f2tf(bR[i].x); Ws[0][r2][cg+1] = f2tf(bR[i].y);
        Ws[0][r2][cg+2] = f2tf(bR[i].z); Ws[0][r2][cg+3] = f2tf(bR[i].w);
    }
    __syncthreads();

    int nT = K >> 4;
    for (int t = 0; t < nT; t++) {
        int cur = t & 1;
        if (t + 1 < nT) {
            int k0 = (t + 1) << 4;
            #pragma unroll
            for (int i = 0; i < 2; i++) {
                int fi = tid + i*256;
                int r = fi >> 2, kg = (fi & 3) << 2;
                aR[i] = *(const float4*)(A + (size_t)(bm + r) * K + k0 + kg);
                int r2 = fi >> 5, cg = (fi & 31) << 2;
                bR[i] = *(const float4*)(W + (size_t)(k0 + r2) * N + bn + cg);
            }
        }
        #pragma unroll
        for (int ks = 0; ks < 16; ks += 8) {
            unsigned af[4][4], bf[4][2];
            #pragma unroll
            for (int mf = 0; mf < 4; mf++) {
                int r0 = wm + mf*16;
                af[mf][0] = Ast[cur][ks+q  ][r0+g  ];
                af[mf][1] = Ast[cur][ks+q  ][r0+g+8];
                af[mf][2] = Ast[cur][ks+q+4][r0+g  ];
                af[mf][3] = Ast[cur][ks+q+4][r0+g+8];
            }
            #pragma unroll
            for (int nf = 0; nf < 4; nf++) {
                int c0 = wn + nf*8;
                bf[nf][0] = Ws[cur][ks+q  ][c0+g];
                bf[nf][1] = Ws[cur][ks+q+4][c0+g];
            }
            #pragma unroll
            for (int mf = 0; mf < 4; mf++)
                #pragma unroll
                for (int nf = 0; nf < 4; nf++)
                    mma_tf32(acc[mf][nf], af[mf], bf[nf]);
        }
        if (t + 1 < nT) {
            int nb = cur ^ 1;
            #pragma unroll
            for (int i = 0; i < 2; i++) {
                int fi = tid + i*256;
                int r = fi >> 2, kg = (fi & 3) << 2;
                Ast[nb][kg+0][r] = f2tf(aR[i].x); Ast[nb][kg+1][r] = f2tf(aR[i].y);
                Ast[nb][kg+2][r] = f2tf(aR[i].z); Ast[nb][kg+3][r] = f2tf(aR[i].w);
                int r2 = fi >> 5, cg = (fi & 31) << 2;
                Ws[nb][r2][cg+0] = f2tf(bR[i].x); Ws[nb][r2][cg+1] = f2tf(bR[i].y);
                Ws[nb][r2][cg+2] = f2tf(bR[i].z); Ws[nb][r2][cg+3] = f2tf(bR[i].w);
            }
        }
        __syncthreads();
    }

    #pragma unroll
    for (int mf = 0; mf < 4; mf++) {
        #pragma unroll
        for (int i = 0; i < 2; i++) {
            int r = bm + wm + mf*16 + g + i*8;
            #pragma unroll
            for (int nf = 0; nf < 4; nf++) {
                int c = bn + wn + nf*8 + 2*q;
                float v0 = acc[mf][nf][i*2+0] * alpha + (bias ? bias[c]   : 0.f);
                float v1 = acc[mf][nf][i*2+1] * alpha + (bias ? bias[c+1] : 0.f);
                if (ACT == 1) {
                    v0 = 0.5f * v0 * (1.f + erff(v0 * 0.70710678118654752f));
                    v1 = 0.5f * v1 * (1.f + erff(v1 * 0.70710678118654752f));
                }
                if (RES) {
                    v0 += resid[(size_t)r * N + c];
                    v1 += resid[(size_t)r * N + c + 1];
                }
                *(float2*)(C + (size_t)r * N + c) = make_float2(v0, v1);
            }
        }
    }
}

// ---------------- legacy fp32 SGEMM (kept for the W-transposed qs GEMM) ----------------
template<int ACT, bool RES, bool WT>
__global__ __launch_bounds__(256)
void sgemm_kernel(const float* __restrict__ A, const float* __restrict__ W,
                  const float* __restrict__ bias, const float* __restrict__ resid,
                  float* __restrict__ C, int M, int N, int K, float alpha) {
    __shared__ float Ast[16][128];
    __shared__ float Ws [16][128];
    int tid = threadIdx.x;
    int tx = tid & 15, ty = tid >> 4;
    int bm = blockIdx.y * 128, bn = blockIdx.x * 128;
    float acc[8][8] = {};
    for (int k0 = 0; k0 < K; k0 += 16) {
        #pragma unroll
        for (int i = 0; i < 2; i++) {
            int fi = tid + i * 256;
            int r = fi >> 2, cg = (fi & 3) << 2;
            float4 va = *(const float4*)(A + (size_t)(bm + r) * K + k0 + cg);
            Ast[cg+0][r] = va.x; Ast[cg+1][r] = va.y;
            Ast[cg+2][r] = va.z; Ast[cg+3][r] = va.w;
        }
        if (!WT) {
            #pragma unroll
            for (int i = 0; i < 2; i++) {
                int fi = tid + i * 256;
                int r = fi >> 5, cg = (fi & 31) << 2;
                *(float4*)(&Ws[r][cg]) = *(const float4*)(W + (size_t)(k0 + r) * N + bn + cg);
            }
        } else {
            #pragma unroll
            for (int i = 0; i < 8; i++) {
                int idx = tid + i * 256;
                int r = idx >> 7, c = idx & 127;
                Ws[r][c] = W[(size_t)(bn + c) * K + k0 + r];
            }
        }
        __syncthreads();
        #pragma unroll
        for (int kk = 0; kk < 16; kk++) {
            float a[8], w[8];
            *(float4*)&a[0] = *(float4*)&Ast[kk][ty*8];
            *(float4*)&a[4] = *(float4*)&Ast[kk][ty*8+4];
            *(float4*)&w[0] = *(float4*)&Ws[kk][tx*8];
            *(float4*)&w[4] = *(float4*)&Ws[kk][tx*8+4];
            #pragma unroll
            for (int i = 0; i < 8; i++)
                #pragma unroll
                for (int j = 0; j < 8; j++)
                    acc[i][j] += a[i] * w[j];
        }
        __syncthreads();
    }
    #pragma unroll
    for (int i = 0; i < 8; i++) {
        int r = bm + ty*8 + i;
        #pragma unroll
        for (int j = 0; j < 8; j++) {
            int c = bn + tx*8 + j;
            float v = acc[i][j] * alpha + (bias ? bias[c] : 0.f);
            if (ACT == 1) v = 0.5f * v * (1.f + erff(v * 0.70710678118654752f));
            if (RES) v += resid[(size_t)r * N + c];
            C[(size_t)r * N + c] = v;
        }
    }
}

// ---------------- RoPE ----------------
__global__ void rope_kernel(float* __restrict__ qkv) {
    int idx = blockIdx.x * 256 + threadIdx.x;
    if (idx >= B_*T_*H_*32) return;
    int d = idx & 31;
    int h = (idx >> 5) & (H_-1);
    int bt = idx >> 7;
    int t = bt & (T_-1);
    float invf = powf(10000.f, -(float)d * (1.f/32.f));
    float ang = (float)t * invf;
    float sv, cv;
    sincosf(ang, &sv, &cv);
    float* base = qkv + (size_t)bt * (3*D_);
    float* qp = base + h * HD_;
    float q1 = qp[d], q2 = qp[d+32];
    qp[d]    = q1*cv - q2*sv;
    qp[d+32] = q2*cv + q1*sv;
    float* kp = base + D_ + h * HD_;
    float k1 = kp[d], k2 = kp[d+32];
    kp[d]    = k1*cv - k2*sv;
    kp[d+32] = k2*cv + k1*sv;
}

// ---------------- tf32 flash attention ----------------
// grid (T/64, H, B), 128 threads (4 warps x 16 rows). FA2 with mma m16n8k8 tf32.
#define ATTN_SMEM2 (4*64*68*4)   // Qs,Ks,Vs,Ps each [64][68] u32 = 69632 B
__global__ __launch_bounds__(128)
void attn_tf32_kernel(const float* __restrict__ qkv, float* __restrict__ out) {
    extern __shared__ unsigned sm[];
    unsigned* Qs = sm;              // [r][d]
    unsigned* Ks = Qs + 64*68;      // [s][d]
    unsigned* Vs = Ks + 64*68;      // [s][d]
    unsigned* Ps = Vs + 64*68;      // [r][s]
    int qt = blockIdx.x, h = blockIdx.y, b = blockIdx.z;
    int tid = threadIdx.x;
    int w = tid >> 5, lane = tid & 31, g = lane >> 2, q = lane & 3;
    int r0 = w * 16;

    // load Q tile (rows qt*64.., dims h*64..)
    const float* qbase = qkv + ((size_t)(b*T_) + qt*64) * (3*D_) + h*HD_;
    #pragma unroll
    for (int i = 0; i < 8; i++) {
        int idx = tid + i*128;                 // 1024 float4s
        int r = idx >> 4, dg = (idx & 15) << 2;
        float4 v = *(const float4*)(qbase + (size_t)r * (3*D_) + dg);
        unsigned* dst = &Qs[r*68 + dg];
        dst[0]=f2tf(v.x); dst[1]=f2tf(v.y); dst[2]=f2tf(v.z); dst[3]=f2tf(v.w);
    }
    float m0 = -INFINITY, m1 = -INFINITY;
    float l0 = 0.f, l1 = 0.f;
    float O[8][4] = {};

    for (int kt = 0; kt <= qt; kt++) {
        __syncthreads();   // prev PV done (and Q ready on first iter) before K/V overwrite
        const float* kbase = qkv + ((size_t)(b*T_) + kt*64) * (3*D_) + D_ + h*HD_;
        #pragma unroll
        for (int i = 0; i < 8; i++) {
            int idx = tid + i*128;
            int r = idx >> 4, dg = (idx & 15) << 2;
            const float* rb = kbase + (size_t)r * (3*D_) + dg;
            float4 kv = *(const float4*)(rb);
            float4 vv = *(const float4*)(rb + D_);
            unsigned* kd = &Ks[r*68 + dg];
            kd[0]=f2tf(kv.x); kd[1]=f2tf(kv.y); kd[2]=f2tf(kv.z); kd[3]=f2tf(kv.w);
            unsigned* vd = &Vs[r*68 + dg];
            vd[0]=f2tf(vv.x); vd[1]=f2tf(vv.y); vd[2]=f2tf(vv.z); vd[3]=f2tf(vv.w);
        }
        __syncthreads();

        // S = Q K^T
        float S[8][4] = {};
        #pragma unroll
        for (int ks = 0; ks < 8; ks++) {
            int k0 = ks*8;
            unsigned af[4];
            af[0] = Qs[(r0+g  )*68 + k0+q  ];
            af[1] = Qs[(r0+g+8)*68 + k0+q  ];
            af[2] = Qs[(r0+g  )*68 + k0+q+4];
            af[3] = Qs[(r0+g+8)*68 + k0+q+4];
            #pragma unroll
            for (int nf = 0; nf < 8; nf++) {
                int s0 = nf*8;
                unsigned bf[2];
                bf[0] = Ks[(s0+g)*68 + k0+q  ];
                bf[1] = Ks[(s0+g)*68 + k0+q+4];
                mma_tf32(S[nf], af, bf);
            }
        }

        // scale + causal mask
        int ra = r0 + g, rb2 = ra + 8;
        #pragma unroll
        for (int nf = 0; nf < 8; nf++) {
            int c = nf*8 + 2*q;
            S[nf][0] *= 0.125f; S[nf][1] *= 0.125f;
            S[nf][2] *= 0.125f; S[nf][3] *= 0.125f;
            if (kt == qt) {
                if (c   > ra ) S[nf][0] = -INFINITY;
                if (c+1 > ra ) S[nf][1] = -INFINITY;
                if (c   > rb2) S[nf][2] = -INFINITY;
                if (c+1 > rb2) S[nf][3] = -INFINITY;
            }
        }
        // online softmax (rows ra, rb2); quad lanes share the row
        float mxa = -INFINITY, mxb = -INFINITY;
        #pragma unroll
        for (int nf = 0; nf < 8; nf++) {
            mxa = fmaxf(mxa, fmaxf(S[nf][0], S[nf][1]));
            mxb = fmaxf(mxb, fmaxf(S[nf][2], S[nf][3]));
        }
        mxa = fmaxf(mxa, __shfl_xor_sync(0xffffffffu, mxa, 1));
        mxa = fmaxf(mxa, __shfl_xor_sync(0xffffffffu, mxa, 2));
        mxb = fmaxf(mxb, __shfl_xor_sync(0xffffffffu, mxb, 1));
        mxb = fmaxf(mxb, __shfl_xor_sync(0xffffffffu, mxb, 2));
        float nm0 = fmaxf(m0, mxa), nm1 = fmaxf(m1, mxb);
        float rf0 = __expf(m0 - nm0), rf1 = __expf(m1 - nm1);
        float sa = 0.f, sb = 0.f;
        #pragma unroll
        for (int nf = 0; nf < 8; nf++) {
            S[nf][0] = __expf(S[nf][0] - nm0);
            S[nf][1] = __expf(S[nf][1] - nm0);
            S[nf][2] = __expf(S[nf][2] - nm1);
            S[nf][3] = __expf(S[nf][3] - nm1);
            sa += S[nf][0] + S[nf][1];
            sb += S[nf][2] + S[nf][3];
        }
        sa += __shfl_xor_sync(0xffffffffu, sa, 1);
        sa += __shfl_xor_sync(0xffffffffu, sa, 2);
        sb += __shfl_xor_sync(0xffffffffu, sb, 1);
        sb += __shfl_xor_sync(0xffffffffu, sb, 2);
        l0 = l0 * rf0 + sa;  l1 = l1 * rf1 + sb;
        m0 = nm0;            m1 = nm1;
        #pragma unroll
        for (int nf = 0; nf < 8; nf++) {
            O[nf][0] *= rf0; O[nf][1] *= rf0;
            O[nf][2] *= rf1; O[nf][3] *= rf1;
        }
        // store P (tf32 bits); each warp owns its own 16 rows
        #pragma unroll
        for (int nf = 0; nf < 8; nf++) {
            int c = nf*8 + 2*q;
            uint2 p0 = make_uint2(f2tf(S[nf][0]), f2tf(S[nf][1]));
            *(uint2*)&Ps[(r0+g  )*68 + c] = p0;
            uint2 p1 = make_uint2(f2tf(S[nf][2]), f2tf(S[nf][3]));
            *(uint2*)&Ps[(r0+g+8)*68 + c] = p1;
        }
        __syncwarp();

        // O += P V
        #pragma unroll
        for (int ss = 0; ss < 8; ss++) {
            int s0 = ss*8;
            unsigned af[4];
            af[0] = Ps[(r0+g  )*68 + s0+q  ];
            af[1] = Ps[(r0+g+8)*68 + s0+q  ];
            af[2] = Ps[(r0+g  )*68 + s0+q+4];
            af[3] = Ps[(r0+g+8)*68 + s0+q+4];
            #pragma unroll
            for (int nf = 0; nf < 8; nf++) {
                unsigned bf[2];
                bf[0] = Vs[(s0+q  )*68 + nf*8+g];
                bf[1] = Vs[(s0+q+4)*68 + nf*8+g];
                mma_tf32(O[nf], af, bf);
            }
        }
    }

    float inv0 = 1.f / l0, inv1 = 1.f / l1;
    float* ob = out + ((size_t)(b*T_) + qt*64 + r0 + g) * D_ + h*HD_;
    #pragma unroll
    for (int nf = 0; nf < 8; nf++) {
        int c = nf*8 + 2*q;
        *(float2*)(ob + c)          = make_float2(O[nf][0]*inv0, O[nf][1]*inv0);
        *(float2*)(ob + 8*D_ + c)   = make_float2(O[nf][2]*inv1, O[nf][3]*inv1);
    }
}

// ---------------- query softmax ----------------
__global__ void qsoftmax_kernel(const float* __restrict__ scores, float* __restrict__ p) {
    int bq = blockIdx.x;
    int b = bq >> 7, q = bq & 127;
    int tid = threadIdx.x;
    __shared__ float red[8];
    float vals[8];
    float lmax = -INFINITY;
    #pragma unroll
    for (int i = 0; i < 8; i++) {
        int t = tid + i*256;
        float s = scores[(size_t)(b*T_ + t) * NQ_ + q];
        vals[i] = s;
        lmax = fmaxf(lmax, s);
    }
    #pragma unroll
    for (int o = 16; o > 0; o >>= 1) lmax = fmaxf(lmax, __shfl_xor_sync(0xffffffffu, lmax, o));
    if ((tid & 31) == 0) red[tid >> 5] = lmax;
    __syncthreads();
    float bmax = -INFINITY;
    #pragma unroll
    for (int i = 0; i < 8; i++) bmax = fmaxf(bmax, red[i]);
    float lsum = 0.f;
    #pragma unroll
    for (int i = 0; i < 8; i++) { vals[i] = expf(vals[i] - bmax); lsum += vals[i]; }
    __syncthreads();
    #pragma unroll
    for (int o = 16; o > 0; o >>= 1) lsum += __shfl_xor_sync(0xffffffffu, lsum, o);
    if ((tid & 31) == 0) red[tid >> 5] = lsum;
    __syncthreads();
    float bsum = 0.f;
    #pragma unroll
    for (int i = 0; i < 8; i++) bsum += red[i];
    float inv = 1.f / bsum;
    #pragma unroll
    for (int i = 0; i < 8; i++)
        p[(size_t)bq * T_ + tid + i*256] = vals[i] * inv;
}

// ---------------- selected ----------------
__global__ void selected_kernel(const float* __restrict__ xf, const float* __restrict__ p,
                                float* __restrict__ sel) {
    int blk = blockIdx.x;
    int b = blk >> 4, qg = (blk & 15) * 8;
    int d = threadIdx.x;
    __shared__ float ps[8][257];
    float acc[8] = {};
    for (int t0 = 0; t0 < T_; t0 += 256) {
        #pragma unroll
        for (int g = 0; g < 8; g++)
            ps[g][threadIdx.x] = p[(size_t)(b*NQ_ + qg + g) * T_ + t0 + threadIdx.x];
        __syncthreads();
        for (int tt = 0; tt < 256; tt++) {
            float xv = xf[(size_t)(b*T_ + t0 + tt) * D_ + d];
            #pragma unroll
            for (int g = 0; g < 8; g++) acc[g] += ps[g][tt] * xv;
        }
        __syncthreads();
    }
    #pragma unroll
    for (int g = 0; g < 8; g++)
        sel[(size_t)(b*NQ_ + qg + g) * D_ + d] = acc[g];
}

// ---------------- bits ----------------
__global__ void bits_kernel(const float* __restrict__ sel, const float* __restrict__ w,
                            const float* __restrict__ b0,
                            float* __restrict__ pairs_out, float* __restrict__ bits_sc) {
    int i = threadIdx.x;
    float s = b0[0];
    const float* sr = sel + (size_t)i * D_;
    for (int d = 0; d < D_; d++) s += sr[d] * w[d];
    float bit = 1.f / (1.f + expf(-s));
    pairs_out[i] = bit;
    bits_sc[i] = bit;
}

// ---------------- sequential MLP scan ----------------
__global__ void scan_kernel(const float* __restrict__ pairs,
                            const float* __restrict__ w1, const float* __restrict__ b1,
                            const float* __restrict__ w2, const float* __restrict__ b2,
                            const float* __restrict__ w3, const float* __restrict__ b3,
                            float* __restrict__ sum_all) {
    int tid = threadIdx.x;
    int bb = tid >> 6, u = tid & 63;
    __shared__ float h1[4][65];
    __shared__ float h2s[4][65];
    __shared__ float carry[4];
    if (u == 0) carry[bb] = 0.f;
    __syncthreads();
    for (int step = 0; step < 64; step++) {
        float a  = pairs[bb*128 + step*2 + 0];
        float bv = pairs[bb*128 + step*2 + 1];
        float cz = carry[bb];
        float h = a*w1[0*64+u] + bv*w1[1*64+u] + cz*w1[2*64+u] + b1[u];
        h1[bb][u] = fmaxf(h, 0.f);
        __syncthreads();
        float h2 = b2[u];
        #pragma unroll 8
        for (int j = 0; j < 64; j++) h2 += h1[bb][j] * w2[j*64+u];
        h2s[bb][u] = fmaxf(h2, 0.f);
        __syncthreads();
        if (u < 2) {
            float o = b3[u];
            #pragma unroll 8
            for (int j = 0; j < 64; j++) o += h2s[bb][j] * w3[j*2+u];
            o = 1.f / (1.f + expf(-o));
            if (u == 0) sum_all[bb*65 + step] = o;
            else        carry[bb] = o;
        }
        __syncthreads();
    }
    if (u == 0) sum_all[bb*65 + 64] = carry[bb];
}

// ---------------- host launcher ----------------
extern "C" void kernel_launch(void* const* d_in, const int* in_sizes, int n_in,
                              void* d_out, int out_size) {
    const int*   tokens = (const int*)  d_in[0];
    const float* embedw = (const float*)d_in[1];
    const float* ln1_w  = (const float*)d_in[2];
    const float* ln1_b  = (const float*)d_in[3];
    const float* qkv_w  = (const float*)d_in[4];
    const float* qkv_b  = (const float*)d_in[5];
    const float* proj_w = (const float*)d_in[6];
    const float* proj_b = (const float*)d_in[7];
    const float* ln2_w  = (const float*)d_in[8];
    const float* ln2_b  = (const float*)d_in[9];
    const float* ffn1_w = (const float*)d_in[10];
    const float* ffn1_b = (const float*)d_in[11];
    const float* ffn2_w = (const float*)d_in[12];
    const float* ffn2_b = (const float*)d_in[13];
    const float* lnf_w  = (const float*)d_in[14];
    const float* lnf_b  = (const float*)d_in[15];
    const float* oq     = (const float*)d_in[16];
    const float* outp_w = (const float*)d_in[17];
    const float* outp_b = (const float*)d_in[18];
    const float* mlp_w1 = (const float*)d_in[19];
    const float* mlp_b1 = (const float*)d_in[20];
    const float* mlp_w2 = (const float*)d_in[21];
    const float* mlp_b2 = (const float*)d_in[22];
    const float* mlp_w3 = (const float*)d_in[23];
    const float* mlp_b3 = (const float*)d_in[24];

    float* out       = (float*)d_out;
    float* out_sum   = out;
    float* out_pairs = out + 260;
    float* out_p     = out + 772;

    float *x, *h, *qkv, *ffn, *sel, *qs, *bits;
    cudaGetSymbolAddress((void**)&x,    g_x);
    cudaGetSymbolAddress((void**)&h,    g_h);
    cudaGetSymbolAddress((void**)&qkv,  g_qkv);
    cudaGetSymbolAddress((void**)&ffn,  g_ffn);
    cudaGetSymbolAddress((void**)&sel,  g_sel);
    cudaGetSymbolAddress((void**)&qs,   g_qs);
    cudaGetSymbolAddress((void**)&bits, g_bits);

    cudaFuncSetAttribute(attn_tf32_kernel, cudaFuncAttributeMaxDynamicSharedMemorySize, ATTN_SMEM2);

    const int M = B_*T_;

    embed_kernel<<<(B_*T_*D_ + 255)/256, 256>>>(tokens, embedw, x);

    for (int l = 0; l < L_; l++) {
        layernorm_kernel<<<M, 256>>>(x, ln1_w + l*D_, ln1_b + l*D_, h);
        gemm_tf32_kernel<0,false><<<dim3(6, 64), 256>>>(
            h, qkv_w + (size_t)l*D_*3*D_, qkv_b + l*3*D_, nullptr, qkv, M, 3*D_, D_, 1.f);
        rope_kernel<<<(B_*T_*H_*32 + 255)/256, 256>>>(qkv);
        attn_tf32_kernel<<<dim3(T_/64, H_, B_), 128, ATTN_SMEM2>>>(qkv, h);
        gemm_tf32_kernel<0,true><<<dim3(2, 64), 256>>>(
            h, proj_w + (size_t)l*D_*D_, proj_b + l*D_, x, x, M, D_, D_, 1.f);
        layernorm_kernel<<<M, 256>>>(x, ln2_w + l*D_, ln2_b + l*D_, h);
        gemm_tf32_kernel<1,false><<<dim3(8, 64), 256>>>(
            h, ffn1_w + (size_t)l*D_*4*D_, ffn1_b + l*4*D_, nullptr, ffn, M, 4*D_, D_, 1.f);
        gemm_tf32_kernel<0,true><<<dim3(2, 64), 256>>>(
            ffn, ffn2_w + (size_t)l*4*D_*D_, ffn2_b + l*D_, x, x, M, D_, 4*D_, 1.f);
    }

    layernorm_kernel<<<M, 256>>>(x, lnf_w, lnf_b, h);

    sgemm_kernel<0,false,true><<<dim3(1, 64), 256>>>(
        h, oq, nullptr, nullptr, qs, M, NQ_, D_, 0.0625f);
    qsoftmax_kernel<<<B_*NQ_, 256>>>(qs, out_p);
    selected_kernel<<<B_*16, 256>>>(h, out_p, sel);
    bits_kernel<<<1, 512>>>(sel, outp_w, outp_b, out_pairs, bits);
    scan_kernel<<<1, 256>>>(bits, mlp_w1, mlp_b1, mlp_w2, mlp_b2, mlp_w3, mlp_b3, out_sum);
}